// round 15
// baseline (speedup 1.0000x reference)
#include <cuda_runtime.h>
#include <cuda_bf16.h>
#include <math.h>

// ---------------- constants ----------------
#define NN 128          // nodes
#define BB 2            // batch
#define VV 1024         // points per batch
#define NP (BB*VV)      // 2048 flattened points
#define GG 8            // node groups
#define NGN (NN/GG)     // 16 nodes per group
#define TPTS 64         // points per CTA tile
#define NTILES (NP/TPTS)// 32

// output layout (floats): c, d, ei, nodes_delta, mean, std
#define OFF_C     0
#define OFF_D     6144
#define OFF_EI    8192
#define OFF_DELTA 16384
#define OFF_MEAN  17152
#define OFF_STD   19200

// ---------------- device scratch (no allocs allowed) ----------------
__device__ float g_ei[NN * BB * 32];          // 32 KB
__device__ float g_mw[NN * NP];               // 1 MB  (mask-applied normalized blend weights)
__device__ float g_partial[(size_t)GG * NP * 256]; // 16 MB
__device__ int   g_maskmode;                  // 0=u8, 1=i32, 2=f32

// ---------------- mask dtype detection ----------------
__global__ void k_detect_mask(const void* mask) {
    if (threadIdx.x != 0 || blockIdx.x != 0) return;
    const float* f = (const float*)mask;
    const int*   ii = (const int*)mask;
    // scanning 1024 "elements" touches at most 4096 bytes; buffer is >= 262144 bytes
    bool f32ok = true, any1 = false;
    for (int i = 0; i < 1024; i++) {
        float v = f[i];
        if (!(v == 0.0f || v == 1.0f)) { f32ok = false; break; }
        if (v == 1.0f) any1 = true;
    }
    if (f32ok && any1) { g_maskmode = 2; return; }
    bool i32ok = true;
    for (int i = 0; i < 1024; i++) {
        int v = ii[i];
        if (v != 0 && v != 1) { i32ok = false; break; }
    }
    g_maskmode = i32ok ? 1 : 0;
}

// ---------------- encode + decode (tiny) ----------------
__global__ void k_encode(const float* __restrict__ t_ped, const float* __restrict__ pose,
                         const float* __restrict__ ec1_w, const float* __restrict__ ec1_b,
                         const float* __restrict__ ec21_w, const float* __restrict__ ec21_b,
                         const float* __restrict__ ec22_w, const float* __restrict__ ec22_b,
                         const float* __restrict__ dc1_w, const float* __restrict__ dc1_b,
                         const float* __restrict__ dc21_w, const float* __restrict__ dc21_b,
                         const float* __restrict__ dc22_w, const float* __restrict__ dc22_b,
                         float* __restrict__ out) {
    int n = blockIdx.x;
    int tid = threadIdx.x; // 64 threads
    __shared__ float enc_in[BB][88], net[BB][64], zz[BB][8], dec_in[BB][80], dnet[BB][64];

    for (int idx = tid; idx < BB * 88; idx += 64) {
        int b = idx / 88, i = idx % 88;
        enc_in[b][i] = (i < 16) ? t_ped[b * 16 + i] : pose[b * 72 + (i - 16)];
    }
    __syncthreads();
    // ec1: Linear(88->64) + relu
    for (int b = 0; b < BB; b++) {
        float a = ec1_b[n * 64 + tid];
        #pragma unroll 4
        for (int i = 0; i < 88; i++) a += enc_in[b][i] * ec1_w[((size_t)n * 88 + i) * 64 + tid];
        net[b][tid] = fmaxf(a, 0.f);
    }
    __syncthreads();
    // ec21 (mean) / ec22 (sigmoid std); z = mean
    if (tid < 16) {
        int b = tid >> 3, o = tid & 7;
        float m = ec21_b[n * 8 + o], s = ec22_b[n * 8 + o];
        for (int i = 0; i < 64; i++) {
            float nv = net[b][i];
            m += nv * ec21_w[((size_t)n * 64 + i) * 8 + o];
            s += nv * ec22_w[((size_t)n * 64 + i) * 8 + o];
        }
        out[OFF_MEAN + (n * BB + b) * 8 + o] = m;
        out[OFF_STD + (n * BB + b) * 8 + o] = 1.0f / (1.0f + expf(-s));
        zz[b][o] = m;
    }
    __syncthreads();
    for (int idx = tid; idx < BB * 80; idx += 64) {
        int b = idx / 80, i = idx % 80;
        dec_in[b][i] = (i < 8) ? zz[b][i] : pose[b * 72 + (i - 8)];
    }
    __syncthreads();
    // dc1: Linear(80->64) + relu
    for (int b = 0; b < BB; b++) {
        float a = dc1_b[n * 64 + tid];
        #pragma unroll 4
        for (int i = 0; i < 80; i++) a += dec_in[b][i] * dc1_w[((size_t)n * 80 + i) * 64 + tid];
        dnet[b][tid] = fmaxf(a, 0.f);
    }
    __syncthreads();
    // dc21 -> ei [b][32]
    {
        int b = tid >> 5, o = tid & 31;
        float e = dc21_b[n * 32 + o];
        for (int i = 0; i < 64; i++) e += dnet[b][i] * dc21_w[((size_t)n * 64 + i) * 32 + o];
        out[OFF_EI + (n * BB + b) * 32 + o] = e;
        g_ei[(n * BB + b) * 32 + o] = e;
    }
    // dc22 -> nodes_delta [b][3]
    if (tid < 6) {
        int b = tid / 3, o = tid % 3;
        float e = dc22_b[n * 3 + o];
        for (int i = 0; i < 64; i++) e += dnet[b][i] * dc22_w[((size_t)n * 64 + i) * 3 + o];
        out[OFF_DELTA + (n * BB + b) * 3 + o] = e;
    }
}

// ---------------- blend-weight normalize + mask fold ----------------
__global__ void k_bwn(const float* __restrict__ bw, const void* __restrict__ mask) {
    int p = blockIdx.x * blockDim.x + threadIdx.x;
    if (p >= NP) return;
    int mode = g_maskmode;
    float s = 0.f;
    for (int n = 0; n < NN; n++) s += bw[(size_t)n * NP + p] + 1e-7f;
    float inv = 1.0f / s;
    for (int n = 0; n < NN; n++) {
        size_t idx = (size_t)n * NP + p;
        bool m;
        if (mode == 0)      m = ((const unsigned char*)mask)[idx] != 0;
        else if (mode == 1) m = ((const int*)mask)[idx] != 0;
        else                m = ((const float*)mask)[idx] != 0.0f;
        g_mw[idx] = m ? (bw[idx] + 1e-7f) * inv : 0.0f;
    }
}

// ---------------- feature field (the big one) ----------------
// smem layout (floats): X[64*95] H1[64*64] H2[64*64] W[6080] Bv[64]
#define SM_X  0
#define SM_H1 6080
#define SM_H2 (6080 + 4096)
#define SM_W  (6080 + 4096 + 4096)
#define SM_B  (6080 + 4096 + 4096 + 6080)
#define SM_FLOATS (6080 + 4096 + 4096 + 6080 + 64)
#define SM_BYTES (SM_FLOATS * 4)

template <int IN>
__device__ __forceinline__ void mlp_layer(const float* __restrict__ Xs,
                                          const float* __restrict__ Ws,
                                          const float* __restrict__ Bs,
                                          float* __restrict__ Os,
                                          int tb, int ob) {
    float a[4][4];
    #pragma unroll
    for (int j = 0; j < 4; j++)
        #pragma unroll
        for (int k = 0; k < 4; k++) a[j][k] = Bs[ob * 4 + k];
    for (int i = 0; i < IN; i++) {
        float4 wv = *reinterpret_cast<const float4*>(Ws + i * 64 + ob * 4);
        #pragma unroll
        for (int j = 0; j < 4; j++) {
            float xv = Xs[(tb * 4 + j) * IN + i];
            a[j][0] += xv * wv.x; a[j][1] += xv * wv.y;
            a[j][2] += xv * wv.z; a[j][3] += xv * wv.w;
        }
    }
    #pragma unroll
    for (int j = 0; j < 4; j++)
        #pragma unroll
        for (int k = 0; k < 4; k++)
            Os[(tb * 4 + j) * 64 + ob * 4 + k] = fmaxf(a[j][k], 0.f);
}

__global__ __launch_bounds__(256, 2)
void k_feature(const float* __restrict__ lc,
               const float* __restrict__ f1w, const float* __restrict__ f1b,
               const float* __restrict__ f2w, const float* __restrict__ f2b,
               const float* __restrict__ f3w, const float* __restrict__ f3b,
               const float* __restrict__ f4w, const float* __restrict__ f4b) {
    extern __shared__ float sm[];
    float* X  = sm + SM_X;
    float* H1 = sm + SM_H1;
    float* H2 = sm + SM_H2;
    float* W  = sm + SM_W;
    float* Bv = sm + SM_B;

    const int tid = threadIdx.x;
    const int tb = tid >> 4;      // 0..15 -> point sub-block
    const int ob = tid & 15;      // 0..15 -> output sub-block
    const int p0 = blockIdx.x * TPTS;
    const int g  = blockIdx.y;

    float accR[4][16];            // [tj][chunk*4 + ok] blend accumulator
    #pragma unroll
    for (int j = 0; j < 4; j++)
        #pragma unroll
        for (int k = 0; k < 16; k++) accR[j][k] = 0.f;

    for (int nn = 0; nn < NGN; nn++) {
        const int n = g * NGN + nn;
        // ---- load X = [ei(32) | local_coords(63)] for 64 points ----
        for (int idx = tid; idx < TPTS * 95; idx += 256) {
            int t = idx / 95, i = idx % 95;
            int p = p0 + t;
            int b = p >> 10, v = p & 1023;
            X[idx] = (i < 32) ? g_ei[(n * BB + b) * 32 + i]
                              : lc[((size_t)(n * BB + b) * VV + v) * 63 + (i - 32)];
        }
        // per-thread masked blend weights for its 4 points
        float mw[4];
        #pragma unroll
        for (int j = 0; j < 4; j++) mw[j] = g_mw[(size_t)n * NP + p0 + tb * 4 + j];

        // ---- layer 1 (95 -> 64) ----
        for (int idx = tid; idx < 95 * 64; idx += 256) W[idx] = f1w[(size_t)n * 95 * 64 + idx];
        if (tid < 64) Bv[tid] = f1b[n * 64 + tid];
        __syncthreads();
        mlp_layer<95>(X, W, Bv, H1, tb, ob);
        __syncthreads();

        // ---- layer 2 (64 -> 64) ----
        for (int idx = tid; idx < 64 * 64; idx += 256) W[idx] = f2w[(size_t)n * 4096 + idx];
        if (tid < 64) Bv[tid] = f2b[n * 64 + tid];
        __syncthreads();
        mlp_layer<64>(H1, W, Bv, H2, tb, ob);
        __syncthreads();

        // ---- layer 3 (64 -> 64) ----
        for (int idx = tid; idx < 64 * 64; idx += 256) W[idx] = f3w[(size_t)n * 4096 + idx];
        if (tid < 64) Bv[tid] = f3b[n * 64 + tid];
        __syncthreads();
        mlp_layer<64>(H2, W, Bv, H1, tb, ob);
        __syncthreads();

        // ---- layer 4 (64 -> 256) in 4 chunks of 64, blend into regs ----
        #pragma unroll 1
        for (int c = 0; c < 4; c++) {
            for (int idx = tid; idx < 64 * 64; idx += 256) {
                int i = idx >> 6, o = idx & 63;
                W[idx] = f4w[((size_t)n * 64 + i) * 256 + c * 64 + o];
            }
            if (tid < 64) Bv[tid] = f4b[n * 256 + c * 64 + tid];
            __syncthreads();
            float a[4][4];
            #pragma unroll
            for (int j = 0; j < 4; j++)
                #pragma unroll
                for (int k = 0; k < 4; k++) a[j][k] = Bv[ob * 4 + k];
            for (int i = 0; i < 64; i++) {
                float4 wv = *reinterpret_cast<const float4*>(W + i * 64 + ob * 4);
                #pragma unroll
                for (int j = 0; j < 4; j++) {
                    float xv = H1[(tb * 4 + j) * 64 + i];
                    a[j][0] += xv * wv.x; a[j][1] += xv * wv.y;
                    a[j][2] += xv * wv.z; a[j][3] += xv * wv.w;
                }
            }
            #pragma unroll
            for (int j = 0; j < 4; j++) {
                #pragma unroll
                for (int k = 0; k < 4; k++) {
                    float v = fmaxf(a[j][k], 0.f);
                    switch (c) {
                        case 0: accR[j][0 + k]  += v * mw[j]; break;
                        case 1: accR[j][4 + k]  += v * mw[j]; break;
                        case 2: accR[j][8 + k]  += v * mw[j]; break;
                        case 3: accR[j][12 + k] += v * mw[j]; break;
                    }
                }
            }
            __syncthreads();
        }
    }

    // ---- write per-group partial blend ----
    #pragma unroll
    for (int j = 0; j < 4; j++) {
        int p = p0 + tb * 4 + j;
        #pragma unroll
        for (int c = 0; c < 4; c++) {
            float4 v = make_float4(accR[j][c * 4 + 0], accR[j][c * 4 + 1],
                                   accR[j][c * 4 + 2], accR[j][c * 4 + 3]);
            *reinterpret_cast<float4*>(&g_partial[((size_t)g * NP + p) * 256 + c * 64 + ob * 4]) = v;
        }
    }
}

// ---------------- reduce partials + NeRF heads ----------------
__global__ void k_heads(const float* __restrict__ c1w, const float* __restrict__ c1b,
                        const float* __restrict__ c2w, const float* __restrict__ c2b,
                        const float* __restrict__ d1w, const float* __restrict__ d1b,
                        float* __restrict__ out) {
    int p = blockIdx.x;     // 0..2047
    int tid = threadIdx.x;  // 256 threads
    __shared__ float fb[256];
    __shared__ float nc[64];

    float s = 0.f;
    #pragma unroll
    for (int g = 0; g < GG; g++) s += g_partial[((size_t)g * NP + p) * 256 + tid];
    fb[tid] = s;
    __syncthreads();

    if (tid < 64) {
        float a = c1b[tid];
        #pragma unroll 4
        for (int i = 0; i < 256; i++) a += fb[i] * c1w[i * 64 + tid];
        nc[tid] = fmaxf(a, 0.f);
    }
    if (tid == 64) {
        float a = d1b[0];
        #pragma unroll 4
        for (int i = 0; i < 256; i++) a += fb[i] * d1w[i];
        out[OFF_D + p] = fmaxf(a, 0.f);
    }
    __syncthreads();
    if (tid < 3) {
        float a = c2b[tid];
        for (int i = 0; i < 64; i++) a += nc[i] * c2w[i * 3 + tid];
        out[OFF_C + p * 3 + tid] = a;
    }
}

// ---------------- launch ----------------
extern "C" void kernel_launch(void* const* d_in, const int* in_sizes, int n_in,
                              void* d_out, int out_size) {
    const float* t_ped  = (const float*)d_in[0];
    const float* pose   = (const float*)d_in[1];
    const float* lc     = (const float*)d_in[2];
    const void*  mask   = d_in[3];
    const float* bw     = (const float*)d_in[4];
    const float* ec1_w  = (const float*)d_in[5];
    const float* ec1_b  = (const float*)d_in[6];
    const float* ec21_w = (const float*)d_in[7];
    const float* ec21_b = (const float*)d_in[8];
    const float* ec22_w = (const float*)d_in[9];
    const float* ec22_b = (const float*)d_in[10];
    const float* dc1_w  = (const float*)d_in[11];
    const float* dc1_b  = (const float*)d_in[12];
    const float* dc21_w = (const float*)d_in[13];
    const float* dc21_b = (const float*)d_in[14];
    const float* dc22_w = (const float*)d_in[15];
    const float* dc22_b = (const float*)d_in[16];
    const float* f1_w   = (const float*)d_in[17];
    const float* f1_b   = (const float*)d_in[18];
    const float* f2_w   = (const float*)d_in[19];
    const float* f2_b   = (const float*)d_in[20];
    const float* f3_w   = (const float*)d_in[21];
    const float* f3_b   = (const float*)d_in[22];
    const float* f4_w   = (const float*)d_in[23];
    const float* f4_b   = (const float*)d_in[24];
    const float* c1_w   = (const float*)d_in[25];
    const float* c1_b   = (const float*)d_in[26];
    const float* c2_w   = (const float*)d_in[27];
    const float* c2_b   = (const float*)d_in[28];
    const float* d1_w   = (const float*)d_in[29];
    const float* d1_b   = (const float*)d_in[30];
    float* out = (float*)d_out;

    static bool attr_done = false;
    if (!attr_done) {
        cudaFuncSetAttribute(k_feature, cudaFuncAttributeMaxDynamicSharedMemorySize, SM_BYTES);
        attr_done = true;
    }

    k_detect_mask<<<1, 32>>>(mask);
    k_encode<<<NN, 64>>>(t_ped, pose, ec1_w, ec1_b, ec21_w, ec21_b, ec22_w, ec22_b,
                         dc1_w, dc1_b, dc21_w, dc21_b, dc22_w, dc22_b, out);
    k_bwn<<<NP / 256, 256>>>(bw, mask);
    k_feature<<<dim3(NTILES, GG), 256, SM_BYTES>>>(lc, f1_w, f1_b, f2_w, f2_b,
                                                   f3_w, f3_b, f4_w, f4_b);
    k_heads<<<NP, 256>>>(c1_w, c1_b, c2_w, c2_b, d1_w, d1_b, out);
}

// round 16
// speedup vs baseline: 1.0358x; 1.0358x over previous
#include <cuda_runtime.h>
#include <cuda_bf16.h>
#include <math.h>

// ---------------- constants ----------------
#define NN 128          // nodes
#define BB 2            // batch
#define VV 1024         // points per batch
#define NP (BB*VV)      // 2048 flattened points
#define GG 8            // node groups
#define NGN (NN/GG)     // 16 nodes per group
#define TPTS 64         // points per CTA tile
#define NTILES (NP/TPTS)// 32

// output layout (floats): c, d, ei, nodes_delta, mean, std
#define OFF_C     0
#define OFF_D     6144
#define OFF_EI    8192
#define OFF_DELTA 16384
#define OFF_MEAN  17152
#define OFF_STD   19200

// ---------------- device scratch (no allocs allowed) ----------------
__device__ float g_ei[NN * BB * 32];          // 32 KB
__device__ float g_mw[NN * NP];               // 1 MB  (mask-applied normalized blend weights)
__device__ float g_partial[(size_t)GG * NP * 256]; // 16 MB
__device__ int   g_maskmode;                  // 0=u8, 1=i32, 2=f32

// ---------------- mask dtype detection ----------------
__global__ void k_detect_mask(const void* mask) {
    if (threadIdx.x != 0 || blockIdx.x != 0) return;
    const float* f = (const float*)mask;
    const int*   ii = (const int*)mask;
    // scanning 1024 "elements" touches at most 4096 bytes; buffer is >= 262144 bytes
    bool f32ok = true, any1 = false;
    for (int i = 0; i < 1024; i++) {
        float v = f[i];
        if (!(v == 0.0f || v == 1.0f)) { f32ok = false; break; }
        if (v == 1.0f) any1 = true;
    }
    if (f32ok && any1) { g_maskmode = 2; return; }
    bool i32ok = true;
    for (int i = 0; i < 1024; i++) {
        int v = ii[i];
        if (v != 0 && v != 1) { i32ok = false; break; }
    }
    g_maskmode = i32ok ? 1 : 0;
}

// ---------------- encode + decode (tiny) ----------------
__global__ void k_encode(const float* __restrict__ t_ped, const float* __restrict__ pose,
                         const float* __restrict__ ec1_w, const float* __restrict__ ec1_b,
                         const float* __restrict__ ec21_w, const float* __restrict__ ec21_b,
                         const float* __restrict__ ec22_w, const float* __restrict__ ec22_b,
                         const float* __restrict__ dc1_w, const float* __restrict__ dc1_b,
                         const float* __restrict__ dc21_w, const float* __restrict__ dc21_b,
                         const float* __restrict__ dc22_w, const float* __restrict__ dc22_b,
                         float* __restrict__ out) {
    int n = blockIdx.x;
    int tid = threadIdx.x; // 64 threads
    __shared__ float enc_in[BB][88], net[BB][64], zz[BB][8], dec_in[BB][80], dnet[BB][64];

    for (int idx = tid; idx < BB * 88; idx += 64) {
        int b = idx / 88, i = idx % 88;
        enc_in[b][i] = (i < 16) ? t_ped[b * 16 + i] : pose[b * 72 + (i - 16)];
    }
    __syncthreads();
    // ec1: Linear(88->64) + relu
    for (int b = 0; b < BB; b++) {
        float a = ec1_b[n * 64 + tid];
        #pragma unroll 4
        for (int i = 0; i < 88; i++) a += enc_in[b][i] * ec1_w[((size_t)n * 88 + i) * 64 + tid];
        net[b][tid] = fmaxf(a, 0.f);
    }
    __syncthreads();
    // ec21 (mean) / ec22 (sigmoid std); z = mean
    if (tid < 16) {
        int b = tid >> 3, o = tid & 7;
        float m = ec21_b[n * 8 + o], s = ec22_b[n * 8 + o];
        for (int i = 0; i < 64; i++) {
            float nv = net[b][i];
            m += nv * ec21_w[((size_t)n * 64 + i) * 8 + o];
            s += nv * ec22_w[((size_t)n * 64 + i) * 8 + o];
        }
        out[OFF_MEAN + (n * BB + b) * 8 + o] = m;
        out[OFF_STD + (n * BB + b) * 8 + o] = 1.0f / (1.0f + expf(-s));
        zz[b][o] = m;
    }
    __syncthreads();
    for (int idx = tid; idx < BB * 80; idx += 64) {
        int b = idx / 80, i = idx % 80;
        dec_in[b][i] = (i < 8) ? zz[b][i] : pose[b * 72 + (i - 8)];
    }
    __syncthreads();
    // dc1: Linear(80->64) + relu
    for (int b = 0; b < BB; b++) {
        float a = dc1_b[n * 64 + tid];
        #pragma unroll 4
        for (int i = 0; i < 80; i++) a += dec_in[b][i] * dc1_w[((size_t)n * 80 + i) * 64 + tid];
        dnet[b][tid] = fmaxf(a, 0.f);
    }
    __syncthreads();
    // dc21 -> ei [b][32]
    {
        int b = tid >> 5, o = tid & 31;
        float e = dc21_b[n * 32 + o];
        for (int i = 0; i < 64; i++) e += dnet[b][i] * dc21_w[((size_t)n * 64 + i) * 32 + o];
        out[OFF_EI + (n * BB + b) * 32 + o] = e;
        g_ei[(n * BB + b) * 32 + o] = e;
    }
    // dc22 -> nodes_delta [b][3]
    if (tid < 6) {
        int b = tid / 3, o = tid % 3;
        float e = dc22_b[n * 3 + o];
        for (int i = 0; i < 64; i++) e += dnet[b][i] * dc22_w[((size_t)n * 64 + i) * 3 + o];
        out[OFF_DELTA + (n * BB + b) * 3 + o] = e;
    }
}

// ---------------- blend-weight normalize + mask fold ----------------
__global__ void k_bwn(const float* __restrict__ bw, const void* __restrict__ mask) {
    int p = blockIdx.x * blockDim.x + threadIdx.x;
    if (p >= NP) return;
    int mode = g_maskmode;
    float s = 0.f;
    for (int n = 0; n < NN; n++) s += bw[(size_t)n * NP + p] + 1e-7f;
    float inv = 1.0f / s;
    for (int n = 0; n < NN; n++) {
        size_t idx = (size_t)n * NP + p;
        bool m;
        if (mode == 0)      m = ((const unsigned char*)mask)[idx] != 0;
        else if (mode == 1) m = ((const int*)mask)[idx] != 0;
        else                m = ((const float*)mask)[idx] != 0.0f;
        g_mw[idx] = m ? (bw[idx] + 1e-7f) * inv : 0.0f;
    }
}

// ---------------- feature field (the big one) ----------------
// smem layout (floats): X[64*95] H1[64*64] H2[64*64] W[6080] Bv[64]
#define SM_X  0
#define SM_H1 6080
#define SM_H2 (6080 + 4096)
#define SM_W  (6080 + 4096 + 4096)
#define SM_B  (6080 + 4096 + 4096 + 6080)
#define SM_FLOATS (6080 + 4096 + 4096 + 6080 + 64)
#define SM_BYTES (SM_FLOATS * 4)

template <int IN>
__device__ __forceinline__ void mlp_layer(const float* __restrict__ Xs,
                                          const float* __restrict__ Ws,
                                          const float* __restrict__ Bs,
                                          float* __restrict__ Os,
                                          int tb, int ob) {
    float a[4][4];
    #pragma unroll
    for (int j = 0; j < 4; j++)
        #pragma unroll
        for (int k = 0; k < 4; k++) a[j][k] = Bs[ob * 4 + k];
    for (int i = 0; i < IN; i++) {
        float4 wv = *reinterpret_cast<const float4*>(Ws + i * 64 + ob * 4);
        #pragma unroll
        for (int j = 0; j < 4; j++) {
            float xv = Xs[(tb * 4 + j) * IN + i];
            a[j][0] += xv * wv.x; a[j][1] += xv * wv.y;
            a[j][2] += xv * wv.z; a[j][3] += xv * wv.w;
        }
    }
    #pragma unroll
    for (int j = 0; j < 4; j++)
        #pragma unroll
        for (int k = 0; k < 4; k++)
            Os[(tb * 4 + j) * 64 + ob * 4 + k] = fmaxf(a[j][k], 0.f);
}

__global__ __launch_bounds__(256, 2)
void k_feature(const float* __restrict__ lc,
               const float* __restrict__ f1w, const float* __restrict__ f1b,
               const float* __restrict__ f2w, const float* __restrict__ f2b,
               const float* __restrict__ f3w, const float* __restrict__ f3b,
               const float* __restrict__ f4w, const float* __restrict__ f4b) {
    extern __shared__ float sm[];
    float* X  = sm + SM_X;
    float* H1 = sm + SM_H1;
    float* H2 = sm + SM_H2;
    float* W  = sm + SM_W;
    float* Bv = sm + SM_B;

    const int tid = threadIdx.x;
    const int tb = tid >> 4;      // 0..15 -> point sub-block
    const int ob = tid & 15;      // 0..15 -> output sub-block
    const int p0 = blockIdx.x * TPTS;
    const int g  = blockIdx.y;

    float accR[4][16];            // [tj][chunk*4 + ok] blend accumulator
    #pragma unroll
    for (int j = 0; j < 4; j++)
        #pragma unroll
        for (int k = 0; k < 16; k++) accR[j][k] = 0.f;

    for (int nn = 0; nn < NGN; nn++) {
        const int n = g * NGN + nn;
        // ---- load X = [ei(32) | local_coords(63)] for 64 points ----
        for (int idx = tid; idx < TPTS * 95; idx += 256) {
            int t = idx / 95, i = idx % 95;
            int p = p0 + t;
            int b = p >> 10, v = p & 1023;
            X[idx] = (i < 32) ? g_ei[(n * BB + b) * 32 + i]
                              : lc[((size_t)(n * BB + b) * VV + v) * 63 + (i - 32)];
        }
        // per-thread masked blend weights for its 4 points
        float mw[4];
        #pragma unroll
        for (int j = 0; j < 4; j++) mw[j] = g_mw[(size_t)n * NP + p0 + tb * 4 + j];

        // ---- layer 1 (95 -> 64) ----
        for (int idx = tid; idx < 95 * 64; idx += 256) W[idx] = f1w[(size_t)n * 95 * 64 + idx];
        if (tid < 64) Bv[tid] = f1b[n * 64 + tid];
        __syncthreads();
        mlp_layer<95>(X, W, Bv, H1, tb, ob);
        __syncthreads();

        // ---- layer 2 (64 -> 64) ----
        for (int idx = tid; idx < 64 * 64; idx += 256) W[idx] = f2w[(size_t)n * 4096 + idx];
        if (tid < 64) Bv[tid] = f2b[n * 64 + tid];
        __syncthreads();
        mlp_layer<64>(H1, W, Bv, H2, tb, ob);
        __syncthreads();

        // ---- layer 3 (64 -> 64) ----
        for (int idx = tid; idx < 64 * 64; idx += 256) W[idx] = f3w[(size_t)n * 4096 + idx];
        if (tid < 64) Bv[tid] = f3b[n * 64 + tid];
        __syncthreads();
        mlp_layer<64>(H2, W, Bv, H1, tb, ob);
        __syncthreads();

        // ---- layer 4 (64 -> 256) in 4 chunks of 64, blend into regs ----
        #pragma unroll 1
        for (int c = 0; c < 4; c++) {
            for (int idx = tid; idx < 64 * 64; idx += 256) {
                int i = idx >> 6, o = idx & 63;
                W[idx] = f4w[((size_t)n * 64 + i) * 256 + c * 64 + o];
            }
            if (tid < 64) Bv[tid] = f4b[n * 256 + c * 64 + tid];
            __syncthreads();
            float a[4][4];
            #pragma unroll
            for (int j = 0; j < 4; j++)
                #pragma unroll
                for (int k = 0; k < 4; k++) a[j][k] = Bv[ob * 4 + k];
            for (int i = 0; i < 64; i++) {
                float4 wv = *reinterpret_cast<const float4*>(W + i * 64 + ob * 4);
                #pragma unroll
                for (int j = 0; j < 4; j++) {
                    float xv = H1[(tb * 4 + j) * 64 + i];
                    a[j][0] += xv * wv.x; a[j][1] += xv * wv.y;
                    a[j][2] += xv * wv.z; a[j][3] += xv * wv.w;
                }
            }
            #pragma unroll
            for (int j = 0; j < 4; j++) {
                #pragma unroll
                for (int k = 0; k < 4; k++) {
                    float v = fmaxf(a[j][k], 0.f);
                    switch (c) {
                        case 0: accR[j][0 + k]  += v * mw[j]; break;
                        case 1: accR[j][4 + k]  += v * mw[j]; break;
                        case 2: accR[j][8 + k]  += v * mw[j]; break;
                        case 3: accR[j][12 + k] += v * mw[j]; break;
                    }
                }
            }
            __syncthreads();
        }
    }

    // ---- write per-group partial blend ----
    #pragma unroll
    for (int j = 0; j < 4; j++) {
        int p = p0 + tb * 4 + j;
        #pragma unroll
        for (int c = 0; c < 4; c++) {
            float4 v = make_float4(accR[j][c * 4 + 0], accR[j][c * 4 + 1],
                                   accR[j][c * 4 + 2], accR[j][c * 4 + 3]);
            *reinterpret_cast<float4*>(&g_partial[((size_t)g * NP + p) * 256 + c * 64 + ob * 4]) = v;
        }
    }
}

// ---------------- reduce partials + NeRF heads ----------------
__global__ void k_heads(const float* __restrict__ c1w, const float* __restrict__ c1b,
                        const float* __restrict__ c2w, const float* __restrict__ c2b,
                        const float* __restrict__ d1w, const float* __restrict__ d1b,
                        float* __restrict__ out) {
    int p = blockIdx.x;     // 0..2047
    int tid = threadIdx.x;  // 256 threads
    __shared__ float fb[256];
    __shared__ float nc[64];

    float s = 0.f;
    #pragma unroll
    for (int g = 0; g < GG; g++) s += g_partial[((size_t)g * NP + p) * 256 + tid];
    fb[tid] = s;
    __syncthreads();

    if (tid < 64) {
        float a = c1b[tid];
        #pragma unroll 4
        for (int i = 0; i < 256; i++) a += fb[i] * c1w[i * 64 + tid];
        nc[tid] = fmaxf(a, 0.f);
    }
    if (tid == 64) {
        float a = d1b[0];
        #pragma unroll 4
        for (int i = 0; i < 256; i++) a += fb[i] * d1w[i];
        out[OFF_D + p] = fmaxf(a, 0.f);
    }
    __syncthreads();
    if (tid < 3) {
        float a = c2b[tid];
        for (int i = 0; i < 64; i++) a += nc[i] * c2w[i * 3 + tid];
        out[OFF_C + p * 3 + tid] = a;
    }
}

// ---------------- launch ----------------
extern "C" void kernel_launch(void* const* d_in, const int* in_sizes, int n_in,
                              void* d_out, int out_size) {
    const float* t_ped  = (const float*)d_in[0];
    const float* pose   = (const float*)d_in[1];
    const float* lc     = (const float*)d_in[2];
    const void*  mask   = d_in[3];
    const float* bw     = (const float*)d_in[4];
    const float* ec1_w  = (const float*)d_in[5];
    const float* ec1_b  = (const float*)d_in[6];
    const float* ec21_w = (const float*)d_in[7];
    const float* ec21_b = (const float*)d_in[8];
    const float* ec22_w = (const float*)d_in[9];
    const float* ec22_b = (const float*)d_in[10];
    const float* dc1_w  = (const float*)d_in[11];
    const float* dc1_b  = (const float*)d_in[12];
    const float* dc21_w = (const float*)d_in[13];
    const float* dc21_b = (const float*)d_in[14];
    const float* dc22_w = (const float*)d_in[15];
    const float* dc22_b = (const float*)d_in[16];
    const float* f1_w   = (const float*)d_in[17];
    const float* f1_b   = (const float*)d_in[18];
    const float* f2_w   = (const float*)d_in[19];
    const float* f2_b   = (const float*)d_in[20];
    const float* f3_w   = (const float*)d_in[21];
    const float* f3_b   = (const float*)d_in[22];
    const float* f4_w   = (const float*)d_in[23];
    const float* f4_b   = (const float*)d_in[24];
    const float* c1_w   = (const float*)d_in[25];
    const float* c1_b   = (const float*)d_in[26];
    const float* c2_w   = (const float*)d_in[27];
    const float* c2_b   = (const float*)d_in[28];
    const float* d1_w   = (const float*)d_in[29];
    const float* d1_b   = (const float*)d_in[30];
    float* out = (float*)d_out;

    static bool attr_done = false;
    if (!attr_done) {
        cudaFuncSetAttribute(k_feature, cudaFuncAttributeMaxDynamicSharedMemorySize, SM_BYTES);
        attr_done = true;
    }

    k_detect_mask<<<1, 32>>>(mask);
    k_encode<<<NN, 64>>>(t_ped, pose, ec1_w, ec1_b, ec21_w, ec21_b, ec22_w, ec22_b,
                         dc1_w, dc1_b, dc21_w, dc21_b, dc22_w, dc22_b, out);
    k_bwn<<<NP / 256, 256>>>(bw, mask);
    k_feature<<<dim3(NTILES, GG), 256, SM_BYTES>>>(lc, f1_w, f1_b, f2_w, f2_b,
                                                   f3_w, f3_b, f4_w, f4_b);
    k_heads<<<NP, 256>>>(c1_w, c1_b, c2_w, c2_b, d1_w, d1_b, out);
}